// round 12
// baseline (speedup 1.0000x reference)
#include <cuda_runtime.h>

// QHadamard: y = FWHT_4096(x) / 64, rows = 8192, DIM = 4096.
// R4/R11 structure (best measured): 3 scalar register passes, 2 smem
// transposes, 0 shuffles.
//   A: bits {5..9}  (thread owns e{0..4} lanes + e{10,11} warp; scalar LDG/STS)
//   B: bits {0..4}  (32 contiguous elem/thread; float4 smem in-place)
//   C: bits {10,11} (float4 smem read; dense float4 STG)
// Swizzle phys(e) = e ^ ((e & 0xE0) >> 3) -- conflict-free in all phases.
// A->B exchange is intra-warp -> __syncwarp; B->C needs the block barrier.
// R12 change: __launch_bounds__(128, 9). The 9-block register budget is
// exactly 56 = this kernel's natural allocation, so we gain a 9th resident
// block (36 warps/SM, +12.5% concurrency) with zero spill risk. (Ladder so
// far: 8 blk/56r = 39.5us; 10 blk/48r = 41.6; 12 blk/40r = 48.0 w/ spills.)

#define DIM 4096
#define THREADS 128

__device__ __forceinline__ void bfly(float& a, float& b) {
    float t = a; a = t + b; b = t - b;
}

__device__ __forceinline__ void fwht32(float* x) {
#pragma unroll
    for (int h = 1; h < 32; h <<= 1)
#pragma unroll
        for (int i = 0; i < 32; i += (h << 1))
#pragma unroll
            for (int j = i; j < i + h; ++j) bfly(x[j], x[j + h]);
}

__global__ void __launch_bounds__(THREADS, 9)
QHadamard_24524263260380_kernel(const float* __restrict__ in,
                                float* __restrict__ out) {
    __shared__ float s[DIM];                      // 16 KB, swizzled layout

    const int    T   = threadIdx.x;               // 0..127
    const size_t row = (size_t)blockIdx.x * DIM;
    const float* g   = in + row;

    // ---- Pass A: e = (T&31) + k*32 + (T>>5)*1024, k = 0..31 -> bits {5..9} ----
    const int abase = (T & 31) + ((T >> 5) << 10);
    float x[32];
#pragma unroll
    for (int k = 0; k < 32; ++k) x[k] = g[abase + (k << 5)];

    const float scale = 0.015625f;                // 1/sqrt(4096)
#pragma unroll
    for (int k = 0; k < 32; ++k) x[k] *= scale;

    fwht32(x);                                    // FWHT over bits 5..9

    // ---- T1 write: s[swz(e)], swz = e ^ ((k&7)<<2). Banks = lane ^ const. ----
#pragma unroll
    for (int k = 0; k < 32; ++k) {
        s[(abase + (k << 5)) ^ ((k & 7) << 2)] = x[k];
    }
    // A->B exchange is intra-warp: warp-local sync suffices.
    __syncwarp(0xffffffffu);

    // ---- Pass B: thread T = e>>5 owns 32 contiguous elements. f4 in/out. ----
    float y[32];
    {
        const int base4 = T * 8;                  // float4 index of e = T*32
        float4* s4 = reinterpret_cast<float4*>(s);
#pragma unroll
        for (int r = 0; r < 8; ++r) {
            float4 v = s4[base4 + (r ^ (T & 7))];
            y[r*4+0] = v.x; y[r*4+1] = v.y; y[r*4+2] = v.z; y[r*4+3] = v.w;
        }
        fwht32(y);                                // FWHT over bits 0..4
#pragma unroll
        for (int r = 0; r < 8; ++r) {
            s4[base4 + (r ^ (T & 7))] =
                make_float4(y[r*4+0], y[r*4+1], y[r*4+2], y[r*4+3]);
        }
    }
    __syncthreads();                              // B->C spans all warps

    // ---- Pass C: base bits{2..6}=T&31, {7,8}=(T>>5)&3; owns {0,1,9,10,11} ----
    const int cbase4 = (T & 31) + (((T >> 5) & 3) << 5);   // float4 index
    const int cxor4  = (T >> 3) & 7;                       // swizzle in f4 units
    float z[32];
    {
        const float4* s4 = reinterpret_cast<const float4*>(s);
#pragma unroll
        for (int rr = 0; rr < 4; ++rr)
#pragma unroll
            for (int s9 = 0; s9 < 2; ++s9) {
                float4 v = s4[(cbase4 + (s9 << 7) + (rr << 8)) ^ cxor4];
                const int i = (rr << 3) + (s9 << 2);
                z[i] = v.x; z[i+1] = v.y; z[i+2] = v.z; z[i+3] = v.w;
            }
    }
    // FWHT over bits {10,11} = z-index bits {3,4}
#pragma unroll
    for (int hi = 0; hi < 32; hi += 16)
#pragma unroll
        for (int j = 0; j < 8; ++j) bfly(z[hi + j], z[hi + j + 8]);
#pragma unroll
    for (int j = 0; j < 16; ++j) bfly(z[j], z[j + 16]);

    // ---- Dense float4 stores: per instr lanes write 32 contiguous float4 ----
    float4* o4 = reinterpret_cast<float4*>(out + row);
#pragma unroll
    for (int rr = 0; rr < 4; ++rr)
#pragma unroll
        for (int s9 = 0; s9 < 2; ++s9) {
            const int i = (rr << 3) + (s9 << 2);
            o4[cbase4 + (s9 << 7) + (rr << 8)] =
                make_float4(z[i], z[i+1], z[i+2], z[i+3]);
        }
}

extern "C" void kernel_launch(void* const* d_in, const int* in_sizes, int n_in,
                              void* d_out, int out_size) {
    const float* x   = (const float*)d_in[0];
    float*       out = (float*)d_out;
    const int rows = in_sizes[0] / DIM;            // 8192
    QHadamard_24524263260380_kernel<<<rows, THREADS>>>(x, out);
}